// round 3
// baseline (speedup 1.0000x reference)
#include <cuda_runtime.h>
#include <cuda_bf16.h>

#define N_NODES  10000
#define N_EDGES  320000
#define IN_DIM   256
#define HIDDEN   256
#define OUT_DIM  128

// ---------------- device scratch (static, 16B-aligned via float4) ----------------
__device__ int    g_idx64;                 // 1 if edge arrays are int64, 0 if int32
__device__ int    g_cnt[N_NODES];
__device__ int    g_rowptr[N_NODES + 1];
__device__ int    g_cursor[N_NODES];
__device__ int    g_src_sorted[N_EDGES];
__device__ float  g_val_sorted[N_EDGES];
__device__ float4 g_Y0[N_NODES * HIDDEN / 4];   // X @ W0
__device__ float4 g_H [N_NODES * HIDDEN / 4];   // relu(A @ Y0)
__device__ float4 g_Y1[N_NODES * OUT_DIM / 4];  // H @ W1

// ---------------- edge index dtype detection ----------------
// If data is int64 with values in [0,10000), every odd 32-bit word is 0.
// If data is int32, odd words are random values in [0,10000) -> P(all 64 zero) ~ 0.
__global__ void detect_kernel(const int* __restrict__ src_words) {
    int is64 = 1;
    #pragma unroll
    for (int i = 0; i < 64; i++)
        if (src_words[2 * i + 1] != 0) { is64 = 0; break; }
    g_idx64 = is64;
}

__device__ __forceinline__ int load_idx(const void* __restrict__ p, int e, int is64) {
    if (is64) return (int)((const long long*)p)[e];
    return ((const int*)p)[e];
}

// ---------------- CSR build ----------------
__global__ void zero_cnt_kernel() {
    int i = blockIdx.x * blockDim.x + threadIdx.x;
    if (i < N_NODES) g_cnt[i] = 0;
}

__global__ void hist_kernel(const void* __restrict__ dst) {
    int e = blockIdx.x * blockDim.x + threadIdx.x;
    int is64 = g_idx64;
    if (e < N_EDGES) {
        int d = load_idx(dst, e, is64);
        atomicAdd(&g_cnt[d], 1);
    }
}

// single-block exclusive scan over 10000 counts
__global__ void scan_kernel() {
    __shared__ int sh[1024];
    __shared__ int carry;
    if (threadIdx.x == 0) carry = 0;
    __syncthreads();
    for (int base = 0; base < N_NODES; base += 1024) {
        int i = base + threadIdx.x;
        int v = (i < N_NODES) ? g_cnt[i] : 0;
        sh[threadIdx.x] = v;
        __syncthreads();
        #pragma unroll
        for (int off = 1; off < 1024; off <<= 1) {
            int t = (threadIdx.x >= off) ? sh[threadIdx.x - off] : 0;
            __syncthreads();
            sh[threadIdx.x] += t;
            __syncthreads();
        }
        int incl = sh[threadIdx.x];
        if (i < N_NODES) {
            int excl = carry + incl - v;
            g_rowptr[i] = excl;
            g_cursor[i] = excl;
        }
        __syncthreads();
        if (threadIdx.x == 1023) carry += sh[1023];
        __syncthreads();
    }
    if (threadIdx.x == 0) g_rowptr[N_NODES] = carry;   // == N_EDGES
}

__global__ void scatter_kernel(const void* __restrict__ src,
                               const void* __restrict__ dst,
                               const float* __restrict__ val) {
    int e = blockIdx.x * blockDim.x + threadIdx.x;
    int is64 = g_idx64;
    if (e < N_EDGES) {
        int d = load_idx(dst, e, is64);
        int s = load_idx(src, e, is64);
        int p = atomicAdd(&g_cursor[d], 1);
        g_src_sorted[p] = s;
        g_val_sorted[p] = val[e];
    }
}

// ---------------- fp32 tiled GEMMs, bound to global scratch ----------------
// BM=64, BN=64, BK=16, 256 threads, 4x4 microtile per thread.

// g_Y0 = features @ W0   (A: harness buffer, C: g_Y0)
__global__ void gemm_XW0_kernel(const float* __restrict__ A,
                                const float* __restrict__ B, int M) {
    const int BM = 64, BN = 64, BK = 16, N = HIDDEN;
    __shared__ float As[BK][BM];
    __shared__ float Bs[BK][BN];
    int bm = blockIdx.y * BM, bn = blockIdx.x * BN, tid = threadIdx.x;
    int arow = tid >> 2, acol = (tid & 3) * 4;
    int brow = tid >> 4, bcol = (tid & 15) * 4;
    int tx = tid & 15, ty = tid >> 4;
    float acc[4][4] = {};
    for (int k0 = 0; k0 < 256; k0 += BK) {
        int gr = bm + arow;
        float4 av = (gr < M) ? *(const float4*)&A[(size_t)gr * 256 + k0 + acol]
                             : make_float4(0.f, 0.f, 0.f, 0.f);
        As[acol + 0][arow] = av.x; As[acol + 1][arow] = av.y;
        As[acol + 2][arow] = av.z; As[acol + 3][arow] = av.w;
        *(float4*)&Bs[brow][bcol] = *(const float4*)&B[(size_t)(k0 + brow) * N + bn + bcol];
        __syncthreads();
        #pragma unroll
        for (int k = 0; k < BK; k++) {
            float a[4], b[4];
            #pragma unroll
            for (int i = 0; i < 4; i++) a[i] = As[k][ty * 4 + i];
            #pragma unroll
            for (int j = 0; j < 4; j++) b[j] = Bs[k][tx * 4 + j];
            #pragma unroll
            for (int i = 0; i < 4; i++)
                #pragma unroll
                for (int j = 0; j < 4; j++)
                    acc[i][j] = fmaf(a[i], b[j], acc[i][j]);
        }
        __syncthreads();
    }
    #pragma unroll
    for (int i = 0; i < 4; i++) {
        int r = bm + ty * 4 + i;
        if (r < M)
            g_Y0[r * (N / 4) + (bn >> 2) + tx] =
                make_float4(acc[i][0], acc[i][1], acc[i][2], acc[i][3]);
    }
}

// g_Y1 = g_H @ W1
__global__ void gemm_HW1_kernel(const float* __restrict__ B, int M) {
    const int BM = 64, BN = 64, BK = 16, N = OUT_DIM;
    __shared__ float As[BK][BM];
    __shared__ float Bs[BK][BN];
    int bm = blockIdx.y * BM, bn = blockIdx.x * BN, tid = threadIdx.x;
    int arow = tid >> 2, acol = (tid & 3) * 4;
    int brow = tid >> 4, bcol = (tid & 15) * 4;
    int tx = tid & 15, ty = tid >> 4;
    float acc[4][4] = {};
    for (int k0 = 0; k0 < 256; k0 += BK) {
        int gr = bm + arow;
        float4 av = (gr < M) ? g_H[gr * 64 + ((k0 + acol) >> 2)]
                             : make_float4(0.f, 0.f, 0.f, 0.f);
        As[acol + 0][arow] = av.x; As[acol + 1][arow] = av.y;
        As[acol + 2][arow] = av.z; As[acol + 3][arow] = av.w;
        *(float4*)&Bs[brow][bcol] = *(const float4*)&B[(size_t)(k0 + brow) * N + bn + bcol];
        __syncthreads();
        #pragma unroll
        for (int k = 0; k < BK; k++) {
            float a[4], b[4];
            #pragma unroll
            for (int i = 0; i < 4; i++) a[i] = As[k][ty * 4 + i];
            #pragma unroll
            for (int j = 0; j < 4; j++) b[j] = Bs[k][tx * 4 + j];
            #pragma unroll
            for (int i = 0; i < 4; i++)
                #pragma unroll
                for (int j = 0; j < 4; j++)
                    acc[i][j] = fmaf(a[i], b[j], acc[i][j]);
        }
        __syncthreads();
    }
    #pragma unroll
    for (int i = 0; i < 4; i++) {
        int r = bm + ty * 4 + i;
        if (r < M)
            g_Y1[r * (N / 4) + (bn >> 2) + tx] =
                make_float4(acc[i][0], acc[i][1], acc[i][2], acc[i][3]);
    }
}

// ---------------- CSR SpMMs (warp per row) ----------------
// g_H = relu(A @ g_Y0), DIM=256 -> 2 float4 per lane
__global__ void spmm1_kernel() {
    const int NV = HIDDEN / 4;   // 64
    int row = blockIdx.x * (blockDim.x >> 5) + (threadIdx.x >> 5);
    if (row >= N_NODES) return;
    int lane = threadIdx.x & 31;
    int e = g_rowptr[row], e_end = g_rowptr[row + 1];
    float4 acc0 = make_float4(0.f, 0.f, 0.f, 0.f);
    float4 acc1 = make_float4(0.f, 0.f, 0.f, 0.f);
    for (; e < e_end; e++) {
        int   src = g_src_sorted[e];
        float v   = g_val_sorted[e];
        const float4* f = g_Y0 + (size_t)src * NV;
        float4 x0 = f[lane];
        float4 x1 = f[lane + 32];
        acc0.x = fmaf(v, x0.x, acc0.x); acc0.y = fmaf(v, x0.y, acc0.y);
        acc0.z = fmaf(v, x0.z, acc0.z); acc0.w = fmaf(v, x0.w, acc0.w);
        acc1.x = fmaf(v, x1.x, acc1.x); acc1.y = fmaf(v, x1.y, acc1.y);
        acc1.z = fmaf(v, x1.z, acc1.z); acc1.w = fmaf(v, x1.w, acc1.w);
    }
    acc0.x = fmaxf(acc0.x, 0.f); acc0.y = fmaxf(acc0.y, 0.f);
    acc0.z = fmaxf(acc0.z, 0.f); acc0.w = fmaxf(acc0.w, 0.f);
    acc1.x = fmaxf(acc1.x, 0.f); acc1.y = fmaxf(acc1.y, 0.f);
    acc1.z = fmaxf(acc1.z, 0.f); acc1.w = fmaxf(acc1.w, 0.f);
    g_H[(size_t)row * NV + lane]      = acc0;
    g_H[(size_t)row * NV + lane + 32] = acc1;
}

// out = A @ g_Y1, DIM=128 -> 1 float4 per lane
__global__ void spmm2_kernel(float4* __restrict__ out) {
    const int NV = OUT_DIM / 4;  // 32
    int row = blockIdx.x * (blockDim.x >> 5) + (threadIdx.x >> 5);
    if (row >= N_NODES) return;
    int lane = threadIdx.x & 31;
    int e = g_rowptr[row], e_end = g_rowptr[row + 1];
    float4 acc = make_float4(0.f, 0.f, 0.f, 0.f);
    for (; e < e_end; e++) {
        int   src = g_src_sorted[e];
        float v   = g_val_sorted[e];
        float4 x = g_Y1[(size_t)src * NV + lane];
        acc.x = fmaf(v, x.x, acc.x); acc.y = fmaf(v, x.y, acc.y);
        acc.z = fmaf(v, x.z, acc.z); acc.w = fmaf(v, x.w, acc.w);
    }
    out[(size_t)row * NV + lane] = acc;
}

// ---------------- launch ----------------
extern "C" void kernel_launch(void* const* d_in, const int* in_sizes, int n_in,
                              void* d_out, int out_size) {
    const float* features = (const float*)d_in[0];
    const void*  edge_src = d_in[1];
    const void*  edge_dst = d_in[2];
    const float* edge_val = (const float*)d_in[3];
    const float* W0       = (const float*)d_in[4];
    const float* W1       = (const float*)d_in[5];
    float4*      out      = (float4*)d_out;

    // 0) detect int32 vs int64 edge index layout
    detect_kernel<<<1, 1>>>((const int*)edge_src);

    // 1) CSR build (by destination)
    zero_cnt_kernel<<<(N_NODES + 255) / 256, 256>>>();
    hist_kernel<<<(N_EDGES + 255) / 256, 256>>>(edge_dst);
    scan_kernel<<<1, 1024>>>();
    scatter_kernel<<<(N_EDGES + 255) / 256, 256>>>(edge_src, edge_dst, edge_val);

    // 2) g_Y0 = X @ W0   (10000x256 @ 256x256)
    {
        dim3 grid(HIDDEN / 64, (N_NODES + 63) / 64);
        gemm_XW0_kernel<<<grid, 256>>>(features, W0, N_NODES);
    }

    // 3) g_H = relu(A @ g_Y0)
    spmm1_kernel<<<(N_NODES + 7) / 8, 256>>>();

    // 4) g_Y1 = g_H @ W1   (10000x256 @ 256x128)
    {
        dim3 grid(OUT_DIM / 64, (N_NODES + 63) / 64);
        gemm_HW1_kernel<<<grid, 256>>>(W1, N_NODES);
    }

    // 5) out = A @ g_Y1
    spmm2_kernel<<<(N_NODES + 7) / 8, 256>>>(out);
}